// round 6
// baseline (speedup 1.0000x reference)
#include <cuda_runtime.h>

#define DD   256
#define HID  1024
#define NL   4
#define NB   16
#define SEQ  4096
#define NC   10

__device__ float g_hA[NB * DD];
__device__ float g_hB[NB * DD];
__device__ float g_v[NB * DD];
__device__ float g_hid[NB * HID];

__device__ __forceinline__ float gelu_tanh(float x) {
    const float k0 = 0.7978845608028654f;   // sqrt(2/pi)
    float x3 = x * x * x;
    return 0.5f * x * (1.0f + tanhf(k0 * (x + 0.044715f * x3)));
}

// 16-lane (same-b group) xor reduction
__device__ __forceinline__ float red16(float v) {
#pragma unroll
    for (int o = 8; o; o >>= 1) v += __shfl_xor_sync(0xffffffffu, v, o);
    return v;
}

// ============ K1: v = LN1(h) @ wv.   grid 64 blocks, 4 cols each ============
// Thread (b = t>>4, g = t&15): batch b, k-chunks c = g+16m (m=0..3).
__global__ __launch_bounds__(256, 1) void k_attn_v(
    const float* __restrict__ W, const float* __restrict__ lns,
    const float* __restrict__ lnb, int first,
    const int* __restrict__ x, const float* __restrict__ emb_tok,
    const float* __restrict__ emb_pos)
{
    __shared__ float4 sh_w[256];
    __shared__ float  sh_S[256], sh_B[256];
    int bk = blockIdx.x, t = threadIdx.x, b = t >> 4, g = t & 15;

    const float4* W4 = (const float4*)W;     // [256 rows][64 quads]
    sh_w[t] = W4[t * 64 + bk];               // column-quad bk, row t
    sh_S[t] = lns[t];
    sh_B[t] = lnb[t];

    float4 hreg[4];
    if (first) {
        int tok = x[b * SEQ];
        const float4* et4 = (const float4*)emb_tok;
        const float4* ep4 = (const float4*)emb_pos;
#pragma unroll
        for (int m = 0; m < 4; ++m) {
            int c = g + 16 * m;
            float4 a = et4[tok * 64 + c], p = ep4[c];
            hreg[m] = make_float4(a.x + p.x, a.y + p.y, a.z + p.z, a.w + p.w);
        }
        if (g == (bk & 15))
            ((float4*)g_hA)[b * 64 + bk] = hreg[bk >> 4];
    } else {
#pragma unroll
        for (int m = 0; m < 4; ++m)
            hreg[m] = ((const float4*)g_hA)[b * 64 + g + 16 * m];
    }

    float s1 = 0.f, s2 = 0.f;
#pragma unroll
    for (int m = 0; m < 4; ++m) {
        s1 += hreg[m].x + hreg[m].y + hreg[m].z + hreg[m].w;
        s2 += hreg[m].x * hreg[m].x + hreg[m].y * hreg[m].y
            + hreg[m].z * hreg[m].z + hreg[m].w * hreg[m].w;
    }
    s1 = red16(s1); s2 = red16(s2);
    float mu = s1 * (1.0f / DD);
    float rs = rsqrtf(fmaxf(s2 * (1.0f / DD) - mu * mu, 0.f) + 1e-5f);

    __syncthreads();

    float4 acc = make_float4(0.f, 0.f, 0.f, 0.f);
#pragma unroll
    for (int m = 0; m < 4; ++m) {
        int c = g + 16 * m;
        float hv[4] = {hreg[m].x, hreg[m].y, hreg[m].z, hreg[m].w};
#pragma unroll
        for (int kk = 0; kk < 4; ++kk) {
            int k = 4 * c + kk;
            float yv = (hv[kk] - mu) * rs * sh_S[k] + sh_B[k];
            float4 wq = sh_w[k];
            acc.x += yv * wq.x; acc.y += yv * wq.y;
            acc.z += yv * wq.z; acc.w += yv * wq.w;
        }
    }
    acc.x = red16(acc.x); acc.y = red16(acc.y);
    acc.z = red16(acc.z); acc.w = red16(acc.w);
    if (g == 0) ((float4*)g_v)[b * 64 + bk] = acc;
}

// ============ K2: hB = hA + v @ wo + bo.   grid 64 ============
__global__ __launch_bounds__(256, 1) void k_attn_o(
    const float* __restrict__ W, const float* __restrict__ bo)
{
    __shared__ float4 sh_w[256];
    int bk = blockIdx.x, t = threadIdx.x, b = t >> 4, g = t & 15;

    const float4* W4 = (const float4*)W;
    sh_w[t] = W4[t * 64 + bk];

    float4 vreg[4];
#pragma unroll
    for (int m = 0; m < 4; ++m)
        vreg[m] = ((const float4*)g_v)[b * 64 + g + 16 * m];

    __syncthreads();

    float4 acc = make_float4(0.f, 0.f, 0.f, 0.f);
#pragma unroll
    for (int m = 0; m < 4; ++m) {
        int c = g + 16 * m;
        float vv[4] = {vreg[m].x, vreg[m].y, vreg[m].z, vreg[m].w};
#pragma unroll
        for (int kk = 0; kk < 4; ++kk) {
            float4 wq = sh_w[4 * c + kk];
            acc.x += vv[kk] * wq.x; acc.y += vv[kk] * wq.y;
            acc.z += vv[kk] * wq.z; acc.w += vv[kk] * wq.w;
        }
    }
    acc.x = red16(acc.x); acc.y = red16(acc.y);
    acc.z = red16(acc.z); acc.w = red16(acc.w);
    if (g == 0) {
        float4 r  = ((const float4*)g_hA)[b * 64 + bk];
        float4 bb = ((const float4*)bo)[bk];
        acc.x += r.x + bb.x; acc.y += r.y + bb.y;
        acc.z += r.z + bb.z; acc.w += r.w + bb.w;
        ((float4*)g_hB)[b * 64 + bk] = acc;
    }
}

// ============ K3: hid = gelu(LN2(hB) @ w1 + b1).   grid 128, 8 cols each ============
__global__ __launch_bounds__(256, 1) void k_mlp_up(
    const float* __restrict__ W, const float* __restrict__ bias,
    const float* __restrict__ lns, const float* __restrict__ lnb)
{
    __shared__ float4 sh_w[512];             // [256 rows][2 quads]
    __shared__ float  sh_S[256], sh_B[256];
    int bk = blockIdx.x, t = threadIdx.x, b = t >> 4, g = t & 15;

    const float4* W14 = (const float4*)W;    // [256 rows][256 quads]
    {
        int e0 = t, k0 = e0 >> 1, q0 = e0 & 1;
        sh_w[e0] = W14[k0 * 256 + bk * 2 + q0];
        int e1 = t + 256, k1 = e1 >> 1, q1 = e1 & 1;
        sh_w[e1] = W14[k1 * 256 + bk * 2 + q1];
    }
    sh_S[t] = lns[t];
    sh_B[t] = lnb[t];

    float4 hreg[4];
#pragma unroll
    for (int m = 0; m < 4; ++m)
        hreg[m] = ((const float4*)g_hB)[b * 64 + g + 16 * m];

    float s1 = 0.f, s2 = 0.f;
#pragma unroll
    for (int m = 0; m < 4; ++m) {
        s1 += hreg[m].x + hreg[m].y + hreg[m].z + hreg[m].w;
        s2 += hreg[m].x * hreg[m].x + hreg[m].y * hreg[m].y
            + hreg[m].z * hreg[m].z + hreg[m].w * hreg[m].w;
    }
    s1 = red16(s1); s2 = red16(s2);
    float mu = s1 * (1.0f / DD);
    float rs = rsqrtf(fmaxf(s2 * (1.0f / DD) - mu * mu, 0.f) + 1e-5f);

    __syncthreads();

    float4 a0 = make_float4(0.f, 0.f, 0.f, 0.f);
    float4 a1 = make_float4(0.f, 0.f, 0.f, 0.f);
#pragma unroll
    for (int m = 0; m < 4; ++m) {
        int c = g + 16 * m;
        float hv[4] = {hreg[m].x, hreg[m].y, hreg[m].z, hreg[m].w};
#pragma unroll
        for (int kk = 0; kk < 4; ++kk) {
            int k = 4 * c + kk;
            float yv = (hv[kk] - mu) * rs * sh_S[k] + sh_B[k];
            float4 w0 = sh_w[k * 2], w1q = sh_w[k * 2 + 1];
            a0.x += yv * w0.x; a0.y += yv * w0.y;
            a0.z += yv * w0.z; a0.w += yv * w0.w;
            a1.x += yv * w1q.x; a1.y += yv * w1q.y;
            a1.z += yv * w1q.z; a1.w += yv * w1q.w;
        }
    }
    a0.x = red16(a0.x); a0.y = red16(a0.y); a0.z = red16(a0.z); a0.w = red16(a0.w);
    a1.x = red16(a1.x); a1.y = red16(a1.y); a1.z = red16(a1.z); a1.w = red16(a1.w);
    if (g == 0) {
        float4 b0 = ((const float4*)bias)[bk * 2];
        float4 b1q = ((const float4*)bias)[bk * 2 + 1];
        float4 g0, g1;
        g0.x = gelu_tanh(a0.x + b0.x); g0.y = gelu_tanh(a0.y + b0.y);
        g0.z = gelu_tanh(a0.z + b0.z); g0.w = gelu_tanh(a0.w + b0.w);
        g1.x = gelu_tanh(a1.x + b1q.x); g1.y = gelu_tanh(a1.y + b1q.y);
        g1.z = gelu_tanh(a1.z + b1q.z); g1.w = gelu_tanh(a1.w + b1q.w);
        ((float4*)g_hid)[b * 256 + bk * 2]     = g0;
        ((float4*)g_hid)[b * 256 + bk * 2 + 1] = g1;
    }
}

// ============ K4: hA = hB + hid @ w2 + b2.   grid 64, 4 cols each ============
__global__ __launch_bounds__(256, 1) void k_mlp_down(
    const float* __restrict__ W, const float* __restrict__ bias)
{
    __shared__ float4 sh_w[1024];            // [1024 rows][1 quad] = 16 KB
    int bk = blockIdx.x, t = threadIdx.x, b = t >> 4, g = t & 15;

    const float4* W24 = (const float4*)W;    // [1024 rows][64 quads]
#pragma unroll
    for (int i = 0; i < 4; ++i)
        sh_w[t + 256 * i] = W24[(t + 256 * i) * 64 + bk];

    float4 hreg[16];
#pragma unroll
    for (int m = 0; m < 16; ++m)
        hreg[m] = ((const float4*)g_hid)[b * 256 + g + 16 * m];

    __syncthreads();

    float4 acc = make_float4(0.f, 0.f, 0.f, 0.f);
#pragma unroll
    for (int m = 0; m < 16; ++m) {
        int c = g + 16 * m;
        float hv[4] = {hreg[m].x, hreg[m].y, hreg[m].z, hreg[m].w};
#pragma unroll
        for (int kk = 0; kk < 4; ++kk) {
            float4 wq = sh_w[4 * c + kk];
            acc.x += hv[kk] * wq.x; acc.y += hv[kk] * wq.y;
            acc.z += hv[kk] * wq.z; acc.w += hv[kk] * wq.w;
        }
    }
    acc.x = red16(acc.x); acc.y = red16(acc.y);
    acc.z = red16(acc.z); acc.w = red16(acc.w);
    if (g == 0) {
        float4 r  = ((const float4*)g_hB)[b * 64 + bk];
        float4 bb = ((const float4*)bias)[bk];
        acc.x += r.x + bb.x; acc.y += r.y + bb.y;
        acc.z += r.z + bb.z; acc.w += r.w + bb.w;
        ((float4*)g_hA)[b * 64 + bk] = acc;
    }
}

// ============ head: out[b,c] = hA[b] . w_cls[:,c] + b_cls[c] ============
__global__ __launch_bounds__(256, 1) void k_head(
    const float* __restrict__ w_cls, const float* __restrict__ b_cls,
    float* __restrict__ out)
{
    __shared__ float sh_h[DD];
    int b = blockIdx.x, t = threadIdx.x;
    sh_h[t] = g_hA[b * DD + t];
    __syncthreads();
    if (t < NC) {
        float acc = b_cls[t];
#pragma unroll 8
        for (int d = 0; d < DD; ++d)
            acc += sh_h[d] * w_cls[d * NC + t];
        out[b * NC + t] = acc;
    }
}

extern "C" void kernel_launch(void* const* d_in, const int* in_sizes, int n_in,
                              void* d_out, int out_size)
{
    // 0:x 1:emb_tok 2:emb_pos 3:proj 4:ln1_s 5:ln1_b 6:wq 7:wk 8:wv 9:wo
    // 10:bo 11:ln2_s 12:ln2_b 13:w1 14:b1 15:w2 16:b2 17:w_cls 18:b_cls
    const int*   x       = (const int*)  d_in[0];
    const float* emb_tok = (const float*)d_in[1];
    const float* emb_pos = (const float*)d_in[2];
    const float* ln1_s   = (const float*)d_in[4];
    const float* ln1_b   = (const float*)d_in[5];
    const float* wv      = (const float*)d_in[8];
    const float* wo      = (const float*)d_in[9];
    const float* bo      = (const float*)d_in[10];
    const float* ln2_s   = (const float*)d_in[11];
    const float* ln2_b   = (const float*)d_in[12];
    const float* w1      = (const float*)d_in[13];
    const float* b1      = (const float*)d_in[14];
    const float* w2      = (const float*)d_in[15];
    const float* b2      = (const float*)d_in[16];
    const float* w_cls   = (const float*)d_in[17];
    const float* b_cls   = (const float*)d_in[18];
    float* out = (float*)d_out;

    for (int l = 0; l < NL; ++l) {
        size_t oDD = (size_t)l * DD * DD;
        k_attn_v<<<64, 256>>>(wv + oDD, ln1_s + l * DD, ln1_b + l * DD,
                              l == 0 ? 1 : 0, x, emb_tok, emb_pos);
        k_attn_o<<<64, 256>>>(wo + oDD, bo + l * DD);
        k_mlp_up<<<128, 256>>>(w1 + (size_t)l * DD * HID, b1 + l * HID,
                               ln2_s + l * DD, ln2_b + l * DD);
        k_mlp_down<<<64, 256>>>(w2 + (size_t)l * HID * DD, b2 + l * DD);
    }
    k_head<<<NB, 256>>>(w_cls, b_cls, out);
}

// round 7
// speedup vs baseline: 2.2111x; 2.2111x over previous
#include <cuda_runtime.h>

#define DD   256
#define HID  1024
#define NL   4
#define NB   16
#define SEQ  4096
#define NC   10

__device__ float g_h[NB * DD];
__device__ float g_v[NB * DD];
__device__ float g_hid[NB * HID];

__device__ __forceinline__ float gelu_tanh(float x) {
    const float k0 = 0.7978845608028654f;   // sqrt(2/pi)
    float x3 = x * x * x;
    return 0.5f * x * (1.0f + tanhf(k0 * (x + 0.044715f * x3)));
}

// Block-wide LayerNorm of a 256-vector (one value per thread) -> sh_y.
__device__ __forceinline__ void block_ln(
    float hval, const float* __restrict__ lns, const float* __restrict__ lnb,
    float* sh_y, float* sh_warp, float* sh_stat, int t)
{
    int lane = t & 31, wid = t >> 5;
    float s1 = hval, s2 = hval * hval;
#pragma unroll
    for (int o = 16; o; o >>= 1) {
        s1 += __shfl_xor_sync(0xffffffffu, s1, o);
        s2 += __shfl_xor_sync(0xffffffffu, s2, o);
    }
    if (lane == 0) { sh_warp[wid] = s1; sh_warp[8 + wid] = s2; }
    __syncthreads();
    if (t == 0) {
        float a = 0.f, c = 0.f;
#pragma unroll
        for (int i = 0; i < 8; ++i) { a += sh_warp[i]; c += sh_warp[8 + i]; }
        float mu = a * (1.0f / DD);
        float var = c * (1.0f / DD) - mu * mu;
        sh_stat[0] = mu;
        sh_stat[1] = rsqrtf(fmaxf(var, 0.f) + 1e-5f);
    }
    __syncthreads();
    sh_y[t] = (hval - sh_stat[0]) * sh_stat[1] * lns[t] + lnb[t];
    __syncthreads();
}

// ============ K1: v = LN1(h) @ wv.  grid 64 = 16 b x 4 quad-groups ============
__global__ __launch_bounds__(256, 1) void k_attn_v(
    const float* __restrict__ W, const float* __restrict__ lns,
    const float* __restrict__ lnb, int first,
    const int* __restrict__ x, const float* __restrict__ emb_tok,
    const float* __restrict__ emb_pos)
{
    __shared__ float  sh_y[DD];
    __shared__ float4 sh_ps[256];
    __shared__ float  sh_warp[16], sh_stat[2];
    int bk = blockIdx.x, t = threadIdx.x;
    int lane = t & 31, w = t >> 5;
    int b = bk >> 2, qq = bk & 3;

    // -------- independent prologue: weight loads (const data) --------
    const float4* W4 = (const float4*)W;   // [256 rows][64 quads]
    int q16 = lane & 15, rh = lane >> 4;
    int jq = qq * 16 + q16;
    int r0 = w * 32 + rh * 16;
    float4 wr[16];
#pragma unroll
    for (int i = 0; i < 16; ++i) wr[i] = W4[(r0 + i) * 64 + jq];

    cudaTriggerProgrammaticLaunchCompletion();
    cudaGridDependencySynchronize();   // predecessor's g_h writes now visible

    float hval;
    if (first) {
        int tok = x[b * SEQ];
        hval = emb_tok[tok * DD + t] + emb_pos[t];
        if (qq == 0) g_h[b * DD + t] = hval;
    } else {
        hval = g_h[b * DD + t];
    }
    block_ln(hval, lns, lnb, sh_y, sh_warp, sh_stat, t);

    float4 acc = make_float4(0.f, 0.f, 0.f, 0.f);
#pragma unroll
    for (int i = 0; i < 16; ++i) {
        float yv = sh_y[r0 + i];
        acc.x += yv * wr[i].x; acc.y += yv * wr[i].y;
        acc.z += yv * wr[i].z; acc.w += yv * wr[i].w;
    }
    sh_ps[(w * 2 + rh) * 16 + q16] = acc;
    __syncthreads();
    if (t < 16) {
        float4 a = sh_ps[t];
#pragma unroll
        for (int s = 1; s < 16; ++s) {
            float4 r = sh_ps[s * 16 + t];
            a.x += r.x; a.y += r.y; a.z += r.z; a.w += r.w;
        }
        ((float4*)(g_v + b * DD))[qq * 16 + t] = a;
    }
}

// ============ K2: h += v @ wo + bo.  grid 64 ============
__global__ __launch_bounds__(256, 1) void k_attn_o(
    const float* __restrict__ W, const float* __restrict__ bo)
{
    __shared__ float  sh_y[DD];
    __shared__ float4 sh_ps[256];
    int bk = blockIdx.x, t = threadIdx.x;
    int lane = t & 31, w = t >> 5;
    int b = bk >> 2, qq = bk & 3;

    const float4* W4 = (const float4*)W;
    int q16 = lane & 15, rh = lane >> 4;
    int jq = qq * 16 + q16;
    int r0 = w * 32 + rh * 16;
    float4 wr[16];
#pragma unroll
    for (int i = 0; i < 16; ++i) wr[i] = W4[(r0 + i) * 64 + jq];

    cudaTriggerProgrammaticLaunchCompletion();
    cudaGridDependencySynchronize();

    sh_y[t] = g_v[b * DD + t];
    __syncthreads();

    float4 acc = make_float4(0.f, 0.f, 0.f, 0.f);
#pragma unroll
    for (int i = 0; i < 16; ++i) {
        float yv = sh_y[r0 + i];
        acc.x += yv * wr[i].x; acc.y += yv * wr[i].y;
        acc.z += yv * wr[i].z; acc.w += yv * wr[i].w;
    }
    sh_ps[(w * 2 + rh) * 16 + q16] = acc;
    __syncthreads();
    if (t < 16) {
        float4 a = sh_ps[t];
#pragma unroll
        for (int s = 1; s < 16; ++s) {
            float4 r = sh_ps[s * 16 + t];
            a.x += r.x; a.y += r.y; a.z += r.z; a.w += r.w;
        }
        float4 ho = ((const float4*)(g_h + b * DD))[qq * 16 + t];
        float4 bb = ((const float4*)bo)[qq * 16 + t];
        a.x += ho.x + bb.x; a.y += ho.y + bb.y;
        a.z += ho.z + bb.z; a.w += ho.w + bb.w;
        ((float4*)(g_h + b * DD))[qq * 16 + t] = a;
    }
}

// ============ K3: hid = gelu(LN2(h) @ w1 + b1).  grid 128 = 16 b x 8 octs ============
__global__ __launch_bounds__(256, 1) void k_mlp_up(
    const float* __restrict__ W, const float* __restrict__ bias,
    const float* __restrict__ lns, const float* __restrict__ lnb)
{
    __shared__ float  sh_y[DD];
    __shared__ float4 sh_ps[256];
    __shared__ float  sh_warp[16], sh_stat[2];
    int bk = blockIdx.x, t = threadIdx.x;
    int lane = t & 31, w = t >> 5;
    int b = bk >> 3, o8 = bk & 7;

    const float4* W14 = (const float4*)W;  // [256 rows][256 quads]
    int jq = o8 * 32 + lane;
    int r0 = w * 32;
    float4 wr[16];
#pragma unroll
    for (int i = 0; i < 16; ++i) wr[i] = W14[(r0 + i) * 256 + jq];

    cudaTriggerProgrammaticLaunchCompletion();
    cudaGridDependencySynchronize();

    block_ln(g_h[b * DD + t], lns, lnb, sh_y, sh_warp, sh_stat, t);

    float4 acc = make_float4(0.f, 0.f, 0.f, 0.f);
#pragma unroll
    for (int i = 0; i < 16; ++i) {
        float yv = sh_y[r0 + i];
        acc.x += yv * wr[i].x; acc.y += yv * wr[i].y;
        acc.z += yv * wr[i].z; acc.w += yv * wr[i].w;
    }
#pragma unroll
    for (int i = 0; i < 16; ++i) wr[i] = W14[(r0 + 16 + i) * 256 + jq];
#pragma unroll
    for (int i = 0; i < 16; ++i) {
        float yv = sh_y[r0 + 16 + i];
        acc.x += yv * wr[i].x; acc.y += yv * wr[i].y;
        acc.z += yv * wr[i].z; acc.w += yv * wr[i].w;
    }
    sh_ps[w * 32 + lane] = acc;
    __syncthreads();
    if (t < 32) {
        float4 a = sh_ps[t];
#pragma unroll
        for (int s = 1; s < 8; ++s) {
            float4 r = sh_ps[s * 32 + t];
            a.x += r.x; a.y += r.y; a.z += r.z; a.w += r.w;
        }
        float4 bb = ((const float4*)bias)[o8 * 32 + t];
        float4 g;
        g.x = gelu_tanh(a.x + bb.x);
        g.y = gelu_tanh(a.y + bb.y);
        g.z = gelu_tanh(a.z + bb.z);
        g.w = gelu_tanh(a.w + bb.w);
        ((float4*)(g_hid + b * HID))[o8 * 32 + t] = g;
    }
}

// ============ K4: h += hid @ w2 + b2.  grid 128 = 16 b x 8 quad-groups ============
__global__ __launch_bounds__(256, 1) void k_mlp_down(
    const float* __restrict__ W, const float* __restrict__ bias)
{
    __shared__ float4 sh_hid4[DD];      // 1024 floats
    __shared__ float4 sh_ps[256];
    __shared__ float4 sh_ps2[64];
    int bk = blockIdx.x, t = threadIdx.x;
    int lane = t & 31, w = t >> 5;
    int b = bk >> 3, g8 = bk & 7;

    const float4* W24 = (const float4*)W;  // [1024 rows][64 quads]
    int q8 = lane & 7, rs = lane >> 3;     // rs 0..3
    int jq = g8 * 8 + q8;
    int r0 = (w * 4 + rs) * 32;            // 32 rows per thread
    float4 wr[16];
#pragma unroll
    for (int i = 0; i < 16; ++i) wr[i] = W24[(r0 + i) * 64 + jq];

    cudaTriggerProgrammaticLaunchCompletion();
    cudaGridDependencySynchronize();

    sh_hid4[t] = ((const float4*)(g_hid + b * HID))[t];
    __syncthreads();
    const float* shid = (const float*)sh_hid4;

    float4 acc = make_float4(0.f, 0.f, 0.f, 0.f);
#pragma unroll
    for (int i = 0; i < 16; ++i) {
        float hv = shid[r0 + i];
        acc.x += hv * wr[i].x; acc.y += hv * wr[i].y;
        acc.z += hv * wr[i].z; acc.w += hv * wr[i].w;
    }
#pragma unroll
    for (int i = 0; i < 16; ++i) wr[i] = W24[(r0 + 16 + i) * 64 + jq];
#pragma unroll
    for (int i = 0; i < 16; ++i) {
        float hv = shid[r0 + 16 + i];
        acc.x += hv * wr[i].x; acc.y += hv * wr[i].y;
        acc.z += hv * wr[i].z; acc.w += hv * wr[i].w;
    }
    sh_ps[(w * 4 + rs) * 8 + q8] = acc;    // [32 segs][8 quads]
    __syncthreads();
    if (t < 64) {
        int sub = t >> 3, q = t & 7;
        float4 a = sh_ps[(sub * 4) * 8 + q];
#pragma unroll
        for (int k = 1; k < 4; ++k) {
            float4 r = sh_ps[(sub * 4 + k) * 8 + q];
            a.x += r.x; a.y += r.y; a.z += r.z; a.w += r.w;
        }
        sh_ps2[sub * 8 + q] = a;
    }
    __syncthreads();
    if (t < 8) {
        float4 a = sh_ps2[t];
#pragma unroll
        for (int s = 1; s < 8; ++s) {
            float4 r = sh_ps2[s * 8 + t];
            a.x += r.x; a.y += r.y; a.z += r.z; a.w += r.w;
        }
        float4 bb = ((const float4*)bias)[g8 * 8 + t];
        float4 ho = ((const float4*)(g_h + b * DD))[g8 * 8 + t];
        a.x += bb.x + ho.x; a.y += bb.y + ho.y;
        a.z += bb.z + ho.z; a.w += bb.w + ho.w;
        ((float4*)(g_h + b * DD))[g8 * 8 + t] = a;
    }
}

// ============ head: out[b,c] = h[b] . w_cls[:,c] + b_cls[c] ============
__global__ __launch_bounds__(256, 1) void k_head(
    const float* __restrict__ w_cls, const float* __restrict__ b_cls,
    float* __restrict__ out)
{
    __shared__ float sh_h[DD];
    int b = blockIdx.x, t = threadIdx.x;
    cudaTriggerProgrammaticLaunchCompletion();
    cudaGridDependencySynchronize();
    sh_h[t] = g_h[b * DD + t];
    __syncthreads();
    if (t < NC) {
        float acc = b_cls[t];
#pragma unroll 8
        for (int d = 0; d < DD; ++d)
            acc += sh_h[d] * w_cls[d * NC + t];
        out[b * NC + t] = acc;
    }
}

// PDL launch helper: successor may start while predecessor still runs;
// cudaGridDependencySynchronize() inside the kernel provides the ordering.
template <typename... Args>
static void launch_pdl(void (*kern)(Args...), int grid, Args... args)
{
    cudaLaunchConfig_t cfg = {};
    cfg.gridDim = {(unsigned)grid, 1, 1};
    cfg.blockDim = {256, 1, 1};
    cfg.dynamicSmemBytes = 0;
    cfg.stream = 0;
    cudaLaunchAttribute attr[1];
    attr[0].id = cudaLaunchAttributeProgrammaticStreamSerialization;
    attr[0].val.programmaticStreamSerializationAllowed = 1;
    cfg.attrs = attr;
    cfg.numAttrs = 1;
    cudaLaunchKernelEx(&cfg, kern, args...);
}

extern "C" void kernel_launch(void* const* d_in, const int* in_sizes, int n_in,
                              void* d_out, int out_size)
{
    // 0:x 1:emb_tok 2:emb_pos 3:proj 4:ln1_s 5:ln1_b 6:wq 7:wk 8:wv 9:wo
    // 10:bo 11:ln2_s 12:ln2_b 13:w1 14:b1 15:w2 16:b2 17:w_cls 18:b_cls
    const int*   x       = (const int*)  d_in[0];
    const float* emb_tok = (const float*)d_in[1];
    const float* emb_pos = (const float*)d_in[2];
    const float* ln1_s   = (const float*)d_in[4];
    const float* ln1_b   = (const float*)d_in[5];
    const float* wv      = (const float*)d_in[8];
    const float* wo      = (const float*)d_in[9];
    const float* bo      = (const float*)d_in[10];
    const float* ln2_s   = (const float*)d_in[11];
    const float* ln2_b   = (const float*)d_in[12];
    const float* w1      = (const float*)d_in[13];
    const float* b1      = (const float*)d_in[14];
    const float* w2      = (const float*)d_in[15];
    const float* b2      = (const float*)d_in[16];
    const float* w_cls   = (const float*)d_in[17];
    const float* b_cls   = (const float*)d_in[18];
    float* out = (float*)d_out;

    for (int l = 0; l < NL; ++l) {
        size_t oDD = (size_t)l * DD * DD;
        launch_pdl(k_attn_v, 64, wv + oDD, ln1_s + l * DD, ln1_b + l * DD,
                   l == 0 ? 1 : 0, x, emb_tok, emb_pos);
        launch_pdl(k_attn_o, 64, wo + oDD, bo + l * DD);
        launch_pdl(k_mlp_up, 128, w1 + (size_t)l * DD * HID, b1 + l * HID,
                   ln2_s + l * DD, ln2_b + l * DD);
        launch_pdl(k_mlp_down, 128, w2 + (size_t)l * HID * DD, b2 + l * DD);
    }
    launch_pdl(k_head, NB, w_cls, b_cls, out);
}